// round 1
// baseline (speedup 1.0000x reference)
#include <cuda_runtime.h>
#include <cstdint>

// Elementwise ReLU, HBM-bound. 16384*8192 fp32 = 2^27 elements.
// Strategy: float4 vectorized grid-stride loop with unrolled independent
// iterations for MLP, grid sized to ~8 waves so the tail imbalance is tiny.

__global__ __launch_bounds__(256) void relu_f4_kernel(
    const float4* __restrict__ in, float4* __restrict__ out, int n4)
{
    int idx = blockIdx.x * blockDim.x + threadIdx.x;
    int stride = gridDim.x * blockDim.x;

    // Main unrolled loop: 4 independent float4 loads in flight per iteration.
    int i = idx;
    #pragma unroll 1
    for (; i + 3 * stride < n4; i += 4 * stride) {
        float4 a = in[i];
        float4 b = in[i + stride];
        float4 c = in[i + 2 * stride];
        float4 d = in[i + 3 * stride];
        a.x = fmaxf(a.x, 0.f); a.y = fmaxf(a.y, 0.f); a.z = fmaxf(a.z, 0.f); a.w = fmaxf(a.w, 0.f);
        b.x = fmaxf(b.x, 0.f); b.y = fmaxf(b.y, 0.f); b.z = fmaxf(b.z, 0.f); b.w = fmaxf(b.w, 0.f);
        c.x = fmaxf(c.x, 0.f); c.y = fmaxf(c.y, 0.f); c.z = fmaxf(c.z, 0.f); c.w = fmaxf(c.w, 0.f);
        d.x = fmaxf(d.x, 0.f); d.y = fmaxf(d.y, 0.f); d.z = fmaxf(d.z, 0.f); d.w = fmaxf(d.w, 0.f);
        out[i] = a;
        out[i + stride] = b;
        out[i + 2 * stride] = c;
        out[i + 3 * stride] = d;
    }
    // Tail
    for (; i < n4; i += stride) {
        float4 a = in[i];
        a.x = fmaxf(a.x, 0.f); a.y = fmaxf(a.y, 0.f); a.z = fmaxf(a.z, 0.f); a.w = fmaxf(a.w, 0.f);
        out[i] = a;
    }
}

// Scalar fallback in case total element count isn't divisible by 4 (not the
// case here: 2^27, but keep kernel_launch general).
__global__ __launch_bounds__(256) void relu_scalar_kernel(
    const float* __restrict__ in, float* __restrict__ out, int n, int start)
{
    int i = start + blockIdx.x * blockDim.x + threadIdx.x;
    if (i < n) out[i] = fmaxf(in[i], 0.f);
}

extern "C" void kernel_launch(void* const* d_in, const int* in_sizes, int n_in,
                              void* d_out, int out_size)
{
    const float* in = (const float*)d_in[0];
    float* out = (float*)d_out;
    int n = in_sizes[0];

    int n4 = n / 4;
    if (n4 > 0) {
        const int threads = 256;
        // 148 SMs * 8 CTAs/SM = enough CTAs for full occupancy; each thread
        // then iterates ~(n4 / (1184*256)) times through the unrolled loop.
        int blocks = 148 * 8;
        int needed = (n4 + threads - 1) / threads;
        if (blocks > needed) blocks = needed;
        relu_f4_kernel<<<blocks, threads>>>(
            (const float4*)in, (float4*)out, n4);
    }
    int rem = n - n4 * 4;
    if (rem > 0) {
        int start = n4 * 4;
        relu_scalar_kernel<<<(rem + 255) / 256, 256>>>(in, out, n, start);
    }
}

// round 5
// speedup vs baseline: 1.0175x; 1.0175x over previous
#include <cuda_runtime.h>
#include <cstdint>

// Elementwise ReLU, HBM-bound streaming kernel.
// 16384*8192 fp32 = 2^27 elements = 1 GiB total traffic (512 MiB R + 512 MiB W).
// R1 ncu: DRAM 78.4%, all pipes idle, occ 88%, issue 5.5% -> purely
// HBM-bound. This round: evict-first streaming hints (.cs) on both loads
// and stores (no reuse -> L2 allocation is pure churn over a 1 GiB stream
// vs 126 MB L2), plus 8x front-batched independent float4 loads per loop
// iteration for deep MLP across the load/store turnaround.

__global__ __launch_bounds__(256) void relu_f4_cs_kernel(
    const float4* __restrict__ in, float4* __restrict__ out, int n4)
{
    const int idx = blockIdx.x * blockDim.x + threadIdx.x;
    const int stride = gridDim.x * blockDim.x;
    const int stride8 = stride * 8;

    int i = idx;
    #pragma unroll 1
    for (; i + 7 * stride < n4; i += stride8) {
        float4 v[8];
        #pragma unroll
        for (int k = 0; k < 8; k++)
            v[k] = __ldcs(&in[i + k * stride]);
        #pragma unroll
        for (int k = 0; k < 8; k++) {
            v[k].x = fmaxf(v[k].x, 0.f);
            v[k].y = fmaxf(v[k].y, 0.f);
            v[k].z = fmaxf(v[k].z, 0.f);
            v[k].w = fmaxf(v[k].w, 0.f);
        }
        #pragma unroll
        for (int k = 0; k < 8; k++)
            __stcs(&out[i + k * stride], v[k]);
    }
    // Tail (n4 = 2^25 here and grid divides evenly, but stay general)
    for (; i < n4; i += stride) {
        float4 a = __ldcs(&in[i]);
        a.x = fmaxf(a.x, 0.f); a.y = fmaxf(a.y, 0.f);
        a.z = fmaxf(a.z, 0.f); a.w = fmaxf(a.w, 0.f);
        __stcs(&out[i], a);
    }
}

__global__ __launch_bounds__(256) void relu_scalar_kernel(
    const float* __restrict__ in, float* __restrict__ out, int n, int start)
{
    int i = start + blockIdx.x * blockDim.x + threadIdx.x;
    if (i < n) out[i] = fmaxf(__ldcs(&in[i]), 0.f);
}

extern "C" void kernel_launch(void* const* d_in, const int* in_sizes, int n_in,
                              void* d_out, int out_size)
{
    const float* in = (const float*)d_in[0];
    float* out = (float*)d_out;
    int n = in_sizes[0];

    int n4 = n / 4;
    if (n4 > 0) {
        const int threads = 256;
        // One full wave: 148 SMs * 8 CTAs/SM (32 regs, 256 thr -> occ 8).
        int blocks = 148 * 8;
        int needed = (n4 + threads - 1) / threads;
        if (blocks > needed) blocks = needed;
        relu_f4_cs_kernel<<<blocks, threads>>>(
            (const float4*)in, (float4*)out, n4);
    }
    int rem = n - n4 * 4;
    if (rem > 0) {
        relu_scalar_kernel<<<(rem + 255) / 256, 256>>>(in, out, n, n4 * 4);
    }
}